// round 12
// baseline (speedup 1.0000x reference)
#include <cuda_runtime.h>
#include <math.h>

#define MD 1024
#define ND 4096
#define BD 16
#define KK 32
#define SMX 512
#define NITER 8
#define TOLSQ (1e-6f * 1e-6f)
#define PAD 68
#define TILE (64 * PAD)

typedef unsigned long long u64_t;
__device__ __forceinline__ void fma2(u64_t &d, u64_t a, u64_t b) {
    asm("fma.rn.f32x2 %0, %1, %2, %0;" : "+l"(d) : "l"(a), "l"(b));
}
__device__ __forceinline__ float acc2sum(u64_t v) {
    float lo, hi; asm("mov.b64 {%0,%1}, %2;" : "=f"(lo), "=f"(hi) : "l"(v)); return lo + hi;
}
__device__ __forceinline__ u64_t pack2(float x) {
    u64_t r; asm("mov.b64 %0, {%1,%1};" : "=l"(r) : "f"(x)); return r;
}
__device__ __forceinline__ void cpa16(float* dst, const float* src) {
    unsigned d = (unsigned)__cvta_generic_to_shared(dst);
    asm volatile("cp.async.cg.shared.global [%0], [%1], 16;" :: "r"(d), "l"(src) : "memory");
}
__device__ __forceinline__ void cpcommit() { asm volatile("cp.async.commit_group;" ::: "memory"); }
__device__ __forceinline__ void cpwait0()  { asm volatile("cp.async.wait_group 0;" ::: "memory"); }
__device__ __forceinline__ void cpwait1()  { asm volatile("cp.async.wait_group 1;" ::: "memory"); }

// ---------------- persistent device state ----------------
__device__ __align__(16) float g_AT[ND][MD];
__device__ __align__(16) float g_rT[MD][BD];
__device__ __align__(16) float g_proxy[BD][ND];
__device__ __align__(16) float g_ATy[BD][ND];       // A^T y (saved from iter-1 proxy)
__device__ unsigned char g_support[BD][ND];
__device__ int   g_suplist[BD][SMX];                // zero-initialized (safe indices)
__device__ int   g_scount[BD], g_sold[BD], g_done[BD];
__device__ __align__(16) float g_P[BD][SMX][MD];    // packed support columns (contiguous rows)
__device__ __align__(16) float g_G[BD][SMX][SMX];   // zero beyond s (invariant)
__device__ __align__(16) float g_H[BD][SMX][SMX];   // zero beyond s (invariant)
__device__ float g_c[BD][SMX];
__device__ __align__(16) float g_T1[BD][SMX][64];   // zeroed each iter (in k_gram)
__device__ __align__(16) float g_Sinv[BD][64][64];

// ---------------- one-time: transpose A ----------------
__global__ void k_transpose(const float* __restrict__ A) {
    __shared__ float tile[32][33];
    int nb = blockIdx.x * 32, mb = blockIdx.y * 32;
    int tx = threadIdx.x, ty = threadIdx.y;
    for (int i = ty; i < 32; i += 8)
        tile[i][tx] = A[(size_t)(mb + i) * ND + nb + tx];
    __syncthreads();
    for (int i = ty; i < 32; i += 8)
        g_AT[nb + i][mb + tx] = tile[tx][i];
}

// ---------------- init ----------------
__global__ void k_init(const float* __restrict__ meas, float* __restrict__ out) {
    long i = (long)blockIdx.x * blockDim.x + threadIdx.x;
    long stride = (long)gridDim.x * blockDim.x;
    float4 z4 = make_float4(0.f, 0.f, 0.f, 0.f);
    long ng = (long)BD * SMX * SMX / 4;
    float4* pg = (float4*)g_G; for (long k = i; k < ng; k += stride) pg[k] = z4;
    float4* ph = (float4*)g_H; for (long k = i; k < ng; k += stride) ph[k] = z4;
    for (long k = i; k < (long)BD * ND; k += stride) {
        g_support[k / ND][k % ND] = 0;
        out[k] = 0.f;
    }
    for (long k = i; k < (long)BD * SMX; k += stride) g_suplist[k / SMX][k % SMX] = 0;
    if (i < BD * MD) { int b = (int)(i / MD), m = (int)(i % MD); g_rT[m][b] = meas[b * MD + m]; }
    if (i < BD) { g_scount[i] = 0; g_sold[i] = 0; g_done[i] = 0; }
}

// ---------------- proxy: proxy[b][n] = sum_m A[m][n] r[m][b]; save=1 also stores ATy ----------------
// grid 128 (n-chunks of 32), block 512 = 32 n-lanes x 16 m-slices
__global__ __launch_bounds__(512) void k_proxy(const float* __restrict__ A, int save) {
    extern __shared__ float smf[];
    u64_t* rsh = (u64_t*)smf;            // [1024][8] u64 = 64KB
    float* psum = smf + 16384;           // [16][32][17]
    int t = threadIdx.x;
    int n0 = blockIdx.x * 32;
    const u64_t* rg = (const u64_t*)g_rT;
    for (int i = t; i < 8192; i += 512) rsh[i] = rg[i];
    __syncthreads();
    int nl = t & 31, mg = t >> 5;
    u64_t acc[8] = {};
    const float* Ac = A + (size_t)(mg * 64) * ND + n0 + nl;
    #pragma unroll 4
    for (int mm = 0; mm < 64; mm++) {
        float a = Ac[(size_t)mm * ND];
        u64_t ad = pack2(a);
        const ulonglong2* rp = (const ulonglong2*)&rsh[(mg * 64 + mm) * 8];
        ulonglong2 r01 = rp[0], r23 = rp[1], r45 = rp[2], r67 = rp[3];
        fma2(acc[0], ad, r01.x); fma2(acc[1], ad, r01.y);
        fma2(acc[2], ad, r23.x); fma2(acc[3], ad, r23.y);
        fma2(acc[4], ad, r45.x); fma2(acc[5], ad, r45.y);
        fma2(acc[6], ad, r67.x); fma2(acc[7], ad, r67.y);
    }
    #pragma unroll
    for (int bp = 0; bp < 8; bp++) {
        float lo, hi; asm("mov.b64 {%0,%1}, %2;" : "=f"(lo), "=f"(hi) : "l"(acc[bp]));
        psum[(mg * 32 + nl) * 17 + 2 * bp]     = lo;
        psum[(mg * 32 + nl) * 17 + 2 * bp + 1] = hi;
    }
    __syncthreads();
    int b = t >> 5, lane = t & 31;
    float s = 0.f;
    #pragma unroll
    for (int m2 = 0; m2 < 16; m2++) s += psum[(m2 * 32 + lane) * 17 + b];
    g_proxy[b][n0 + lane] = s;
    if (save) g_ATy[b][n0 + lane] = s;
}

// ---------------- suffix-scan boundary select over 2048 buckets ----------------
__device__ __forceinline__ void suffix_select(const int* hist, int need, int t, int lane, int wd,
                                              int* wtot, int* outB, int* outNeed) {
    int base = 2047 - 4 * t;
    int c[4];
    #pragma unroll
    for (int q = 0; q < 4; q++) c[q] = hist[base - q];
    int ssum = c[0] + c[1] + c[2] + c[3];
    int incl = ssum;
    #pragma unroll
    for (int off = 1; off < 32; off <<= 1) {
        int v = __shfl_up_sync(0xffffffffu, incl, off);
        if (lane >= off) incl += v;
    }
    if (lane == 31) wtot[wd] = incl;
    __syncthreads();
    int wpre = 0;
    #pragma unroll
    for (int w = 0; w < 16; w++) if (w < wd) wpre += wtot[w];
    incl += wpre;
    int excl = incl - ssum;
    if (excl < need && need <= incl) {
        int cum = excl;
        #pragma unroll
        for (int q = 0; q < 4; q++) {
            cum += c[q];
            if (cum >= need) { *outB = base - q; *outNeed = need - (cum - c[q]); break; }
        }
    }
    __syncthreads();
}

// ---------------- topk: 3-pass radix + support update + c gather ----------------
// grid BD, block 512
__global__ __launch_bounds__(512) void k_topk(void) {
    int b = blockIdx.x;
    if (g_done[b]) return;
    extern __shared__ float smf[];
    unsigned* keys = (unsigned*)smf;           // [4096]
    int* cand = (int*)(smf + 4096);            // [4096]
    __shared__ int hist[2048];
    __shared__ int wtot[16];
    __shared__ int sh_B, sh_need, sh_L;
    __shared__ int sh_app, sh_sold, sh_neq;
    __shared__ int eqlist[128];
    int t = threadIdx.x, lane = t & 31, wd = t >> 5;
    for (int n = t; n < ND; n += 512) keys[n] = __float_as_uint(fabsf(g_proxy[b][n]));
    for (int i = t; i < 2048; i += 512) hist[i] = 0;
    if (t == 0) { sh_sold = g_scount[b]; sh_app = sh_sold; sh_neq = 0; sh_L = 0; }
    __syncthreads();
    // pass 1: bits 31..21, warp-aggregated atomics
    for (int n = t; n < ND; n += 512) {
        unsigned d = keys[n] >> 21;
        unsigned mk = __match_any_sync(0xffffffffu, d);
        if ((mk & ((1u << lane) - 1)) == 0) atomicAdd(&hist[d], __popc(mk));
    }
    __syncthreads();
    suffix_select(hist, 2 * KK, t, lane, wd, wtot, &sh_B, &sh_need);
    unsigned pref = (unsigned)sh_B << 21;
    int need = sh_need;
    __syncthreads();
    for (int n = t; n < ND; n += 512)
        if ((keys[n] >> 21) == (pref >> 21)) { int p = atomicAdd(&sh_L, 1); cand[p] = n; }
    __syncthreads();
    int L = sh_L;
    // pass 2: bits 20..10 over candidates
    for (int i = t; i < 2048; i += 512) hist[i] = 0;
    __syncthreads();
    for (int i = t; i < L; i += 512) atomicAdd(&hist[(keys[cand[i]] >> 10) & 2047u], 1);
    __syncthreads();
    suffix_select(hist, need, t, lane, wd, wtot, &sh_B, &sh_need);
    pref |= (unsigned)sh_B << 10;
    need = sh_need;
    __syncthreads();
    // pass 3: bits 9..0
    for (int i = t; i < 2048; i += 512) hist[i] = 0;
    __syncthreads();
    for (int i = t; i < L; i += 512) {
        unsigned k = keys[cand[i]];
        if ((k >> 10) == (pref >> 10)) atomicAdd(&hist[k & 1023u], 1);
    }
    __syncthreads();
    suffix_select(hist, need, t, lane, wd, wtot, &sh_B, &sh_need);
    unsigned T = pref | (unsigned)sh_B;
    need = sh_need;
    __syncthreads();
    // select key > T (unordered append; slot order irrelevant to the linear algebra)
    for (int n = t; n < ND; n += 512) {
        if (keys[n] > T && !g_support[b][n]) {
            g_support[b][n] = 1;
            int p = atomicAdd(&sh_app, 1);
            g_suplist[b][p] = n;
        }
    }
    for (int i = t; i < L; i += 512) {
        int n = cand[i];
        if (keys[n] == T) { int q = atomicAdd(&sh_neq, 1); if (q < 128) eqlist[q] = n; }
    }
    __syncthreads();
    if (t == 0) {
        int ne = sh_neq < 128 ? sh_neq : 128;
        for (int r = 0; r < need; r++) {           // jax ties: smallest index first
            int best = 0x7fffffff, bi = -1;
            for (int q = 0; q < ne; q++) { int n = eqlist[q]; if (n >= 0 && n < best) { best = n; bi = q; } }
            if (bi < 0) break;
            eqlist[bi] = -1;
            if (!g_support[b][best]) { g_support[b][best] = 1; g_suplist[b][sh_app++] = best; }
        }
        g_sold[b] = sh_sold;
        g_scount[b] = sh_app;
    }
    __syncthreads();
    // c for new slots: gather from ATy (c_p = (A^T y)[col])
    int so = sh_sold, s = sh_app;
    for (int p = so + t; p < s; p += 512)
        g_c[b][p] = g_ATy[b][g_suplist[b][p]];
}

// ---------------- pack: one block per new column, pure copy ----------------
// grid (BD, 64), block 128
__global__ void k_pack(void) {
    int b = blockIdx.x;
    if (g_done[b]) return;
    int so = g_sold[b], s = g_scount[b];
    int p = so + blockIdx.y;
    if (p >= s) return;
    int col = g_suplist[b][p];
    int t = threadIdx.x;
    const float4* Ac = (const float4*)g_AT[col];
    float4* Pd = (float4*)g_P[b][p];
    #pragma unroll
    for (int i = 0; i < 2; i++) Pd[t + 128 * i] = Ac[t + 128 * i];
}

// ======== 64x64 microkernel: 512 thr, 2x4 accs, conflict-free LDS.128 ========
#define MICRO(AS, BS, ACC)                                                     \
    {                                                                          \
        _Pragma("unroll")                                                      \
        for (int k4 = 0; k4 < 16; k4++) {                                      \
            ulonglong2 rv[2], cv[4];                                           \
            _Pragma("unroll")                                                  \
            for (int i = 0; i < 2; i++)                                        \
                rv[i] = *(const ulonglong2*)&(AS)[(ty + 32 * i) * PAD + k4 * 4]; \
            _Pragma("unroll")                                                  \
            for (int j = 0; j < 4; j++)                                        \
                cv[j] = *(const ulonglong2*)&(BS)[(tx + 16 * j) * PAD + k4 * 4]; \
            _Pragma("unroll")                                                  \
            for (int i = 0; i < 2; i++)                                        \
                _Pragma("unroll")                                              \
                for (int j = 0; j < 4; j++) {                                  \
                    fma2(ACC[i][j], rv[i].x, cv[j].x);                         \
                    fma2(ACC[i][j], rv[i].y, cv[j].y);                         \
                }                                                              \
        }                                                                      \
    }

// pipelined 64xNSx64 GEMM with uniform row strides
__device__ __forceinline__ void pipe_gemm(const float* A0, int As_, const float* B0, int Bs_,
                                          int NS, float* sm, u64_t (&acc)[2][4],
                                          int t, int ty, int tx) {
    float* Ab = sm; float* Bb = sm + 2 * TILE;
    #pragma unroll
    for (int q = 0; q < 2; q++) {
        int idx = t + 512 * q; int r = idx >> 4, f = (idx & 15) * 4;
        cpa16(&Ab[r * PAD + f], A0 + (long)r * As_ + f);
        cpa16(&Bb[r * PAD + f], B0 + (long)r * Bs_ + f);
    }
    cpcommit();
    for (int step = 0; step < NS; step++) {
        int cur = step & 1;
        if (step + 1 < NS) {
            int k0 = (step + 1) * 64;
            #pragma unroll
            for (int q = 0; q < 2; q++) {
                int idx = t + 512 * q; int r = idx >> 4, f = (idx & 15) * 4;
                cpa16(&Ab[(cur ^ 1) * TILE + r * PAD + f], A0 + (long)r * As_ + k0 + f);
                cpa16(&Bb[(cur ^ 1) * TILE + r * PAD + f], B0 + (long)r * Bs_ + k0 + f);
            }
            cpcommit(); cpwait1();
        } else cpwait0();
        __syncthreads();
        const float* As = Ab + cur * TILE;
        const float* Bs = Bb + cur * TILE;
        MICRO(As, Bs, acc)
        __syncthreads();
    }
}

// ---------------- gram: contiguous g_P rows, k-split 4, atomic accumulate ----------------
// grid (BD, 8, 4), block 512
__global__ __launch_bounds__(512) void k_gram(void) {
    int b = blockIdx.x;
    if (g_done[b]) return;
    int so = g_sold[b], s = g_scount[b], nn = s - so;
    if (nn == 0) return;
    int t = threadIdx.x;
    if (blockIdx.y == 0 && blockIdx.z == 0) {   // zero T1 for the next kernel
        float4 z4 = make_float4(0.f, 0.f, 0.f, 0.f);
        float4* p = (float4*)g_T1[b];
        for (int i = t; i < SMX * 64 / 4; i += 512) p[i] = z4;
    }
    int c0 = blockIdx.y * 64;
    if (c0 >= s) return;
    extern __shared__ float sm[];
    int ty = t >> 4, tx = t & 15;
    int kz = blockIdx.z * 256;
    int soc = so < SMX - 64 ? so : SMX - 64;   // clamp row base (garbage never stored)
    u64_t acc[2][4] = {};
    pipe_gemm(&g_P[b][soc][kz], MD, &g_P[b][c0][kz], MD, 4, sm, acc, t, ty, tx);
    int dso = so - soc;
    #pragma unroll
    for (int i = 0; i < 2; i++) {
        int r = ty + 32 * i - dso; if (r < 0 || r >= nn) continue;
        #pragma unroll
        for (int j = 0; j < 4; j++) {
            int c = c0 + tx + 16 * j; if (c >= s) continue;
            float v = acc2sum(acc[i][j]);
            atomicAdd(&g_G[b][so + r][c], v);
            if (c < so) atomicAdd(&g_G[b][c][so + r], v);  // mirror (new-new covered directly)
        }
    }
}

// ---------------- T1: k-split 2, atomic into pre-zeroed T1 ----------------
// grid (BD, 8, 2), block 512
__global__ __launch_bounds__(512) void k_T1(void) {
    int b = blockIdx.x;
    if (g_done[b]) return;
    int so = g_sold[b], s = g_scount[b], nn = s - so;
    if (nn == 0) return;
    int r0 = blockIdx.y * 64;
    if (r0 >= so) return;
    int NS = (so + 63) >> 6;
    int nsa = (NS + 1) >> 1;
    int base = (blockIdx.z == 0) ? 0 : nsa;
    int steps = (blockIdx.z == 0) ? nsa : NS - nsa;
    if (steps <= 0) return;
    extern __shared__ float sm[];
    int t = threadIdx.x, ty = t >> 4, tx = t & 15;
    int soc = so < SMX - 64 ? so : SMX - 64;
    u64_t acc[2][4] = {};
    pipe_gemm(&g_G[b][soc][base * 64], SMX, &g_H[b][r0][base * 64], SMX, steps, sm, acc, t, ty, tx);
    int dso = so - soc;
    #pragma unroll
    for (int i = 0; i < 2; i++) {
        int c = ty + 32 * i - dso; if (c < 0 || c >= 64) continue;
        #pragma unroll
        for (int j = 0; j < 4; j++)
            atomicAdd(&g_T1[b][r0 + tx + 16 * j][c], acc2sum(acc[i][j]));
    }
}

// ---------------- SSinv: pipelined S = G22 - G21 T1 -> GJ inverse -> Sinv, H22 ----------------
// grid BD, block 512, dyn smem 4*TILE floats
__global__ __launch_bounds__(512) void k_SSinv(void) {
    int b = blockIdx.x;
    if (g_done[b]) return;
    int so = g_sold[b], s = g_scount[b], nn = s - so;
    if (nn == 0) return;
    extern __shared__ float sm[];
    float* Ab = sm; float* Bb = sm + 2 * TILE;
    __shared__ float Ssm[64][65];
    __shared__ float pivrow[128], fcol[64], sh_piv;
    int t = threadIdx.x;
    int i = t >> 3, jg = t & 7;
    int soc = so < SMX - 64 ? so : SMX - 64;   // row clamp; extra rows pair with zero T1
    int dso = so - soc;
    float accs[8] = {};
    int NS = (so + 63) >> 6;
    if (NS > 0) {
        #pragma unroll
        for (int q = 0; q < 2; q++) {
            int idx = t + 512 * q; int r = idx >> 4, f = (idx & 15) * 4;
            cpa16(&Ab[r * PAD + f], &g_G[b][soc + r][f]);
            cpa16(&Bb[r * PAD + f], &g_T1[b][r][f]);
        }
        cpcommit();
        for (int step = 0; step < NS; step++) {
            int cur = step & 1;
            if (step + 1 < NS) {
                int k0 = (step + 1) * 64;
                #pragma unroll
                for (int q = 0; q < 2; q++) {
                    int idx = t + 512 * q; int r = idx >> 4, f = (idx & 15) * 4;
                    cpa16(&Ab[(cur ^ 1) * TILE + r * PAD + f], &g_G[b][soc + r][k0 + f]);
                    cpa16(&Bb[(cur ^ 1) * TILE + r * PAD + f], &g_T1[b][k0 + r][f]);
                }
                cpcommit(); cpwait1();
            } else cpwait0();
            __syncthreads();
            const float* As = Ab + cur * TILE;
            const float* Bs = Bb + cur * TILE;
            int ri = i + dso;   // smem row for logical S row i
            #pragma unroll 8
            for (int k = 0; k < 64; k++) {
                float gv = (ri < 64) ? As[ri * PAD + k] : 0.f;
                #pragma unroll
                for (int jj = 0; jj < 8; jj++) accs[jj] = fmaf(gv, Bs[k * PAD + jg * 8 + jj], accs[jj]);
            }
            __syncthreads();
        }
    }
    // handle rows beyond clamp window (so close to SMX-64: dso>0 -> rows i >= 64-dso)
    if (dso > 0 && i + dso >= 64) {
        // recompute serially from global (rare tail; nn <= 64 ensures i < nn only matters)
        #pragma unroll
        for (int jj = 0; jj < 8; jj++) accs[jj] = 0.f;
        for (int k = 0; k < so; k++) {
            float gv = g_G[b][so + i][k];
            #pragma unroll
            for (int jj = 0; jj < 8; jj++) accs[jj] = fmaf(gv, g_T1[b][k][jg * 8 + jj], accs[jj]);
        }
    }
    #pragma unroll
    for (int jj = 0; jj < 8; jj++) {
        int j = jg * 8 + jj;
        float v;
        if (i < nn && j < nn) v = g_G[b][so + i][so + j] - accs[jj];
        else v = (i == j) ? 1.f : 0.f;
        Ssm[i][j] = v;
    }
    __syncthreads();
    int row = t >> 3, cg = t & 7;
    float a[16];
    #pragma unroll
    for (int cc = 0; cc < 16; cc++) {
        int c = cg * 16 + cc;
        a[cc] = (c < 64) ? Ssm[row][c] : ((c - 64 == row) ? 1.f : 0.f);
    }
    __syncthreads();
    for (int j = 0; j < 64; j++) {
        if (row == j && cg == (j >> 4)) sh_piv = a[j & 15];
        __syncthreads();
        float inv = 1.f / sh_piv;
        if (row == j) {
            #pragma unroll
            for (int cc = 0; cc < 16; cc++) { a[cc] *= inv; pivrow[cg * 16 + cc] = a[cc]; }
        }
        if (cg == (j >> 4)) fcol[row] = a[j & 15];
        __syncthreads();
        float f = (row == j) ? 0.f : fcol[row];
        #pragma unroll
        for (int cc = 0; cc < 16; cc++) a[cc] = fmaf(-f, pivrow[cg * 16 + cc], a[cc]);
    }
    __syncthreads();
    #pragma unroll
    for (int cc = 0; cc < 16; cc++) {
        int c = cg * 16 + cc;
        if (c >= 64) {
            int j = c - 64;
            g_Sinv[b][row][j] = a[cc];
            if (row < nn && j < nn) g_H[b][so + row][so + j] = a[cc];
        }
    }
}

// ---------------- T2 + H11 (c-split 2, disjoint tiles) ----------------
// grid (BD, 8, 2), block 512
__global__ __launch_bounds__(512) void k_T2H11(void) {
    int b = blockIdx.x;
    if (g_done[b]) return;
    int so = g_sold[b], s = g_scount[b], nn = s - so;
    if (nn == 0) return;
    int r0 = blockIdx.y * 64;
    if (r0 >= so) return;
    int NSB = (so + 63) >> 6;
    int nsa = (NSB + 1) >> 1;
    int cbase = (blockIdx.z == 0) ? 0 : nsa;
    int csteps = (blockIdx.z == 0) ? nsa : NSB - nsa;
    if (csteps <= 0) return;
    extern __shared__ float sm[];
    float* As = sm; float* Bb = sm + TILE;
    int t = threadIdx.x, ty = t >> 4, tx = t & 15;
    // phase A: T2[r][c] = sum_k T1[r][k] Sinv[c][k]
    #pragma unroll
    for (int q = 0; q < 2; q++) {
        int idx = t + 512 * q; int r = idx >> 4, f = (idx & 15) * 4;
        cpa16(&As[r * PAD + f], &g_T1[b][r0 + r][f]);
        cpa16(&Bb[r * PAD + f], &g_Sinv[b][r][f]);
    }
    cpcommit(); cpwait0();
    __syncthreads();
    u64_t acc[2][4] = {};
    MICRO(As, Bb, acc)
    float t2v[2][4];
    #pragma unroll
    for (int i = 0; i < 2; i++)
        #pragma unroll
        for (int j = 0; j < 4; j++) t2v[i][j] = acc2sum(acc[i][j]);
    if (blockIdx.z == 0) {
        #pragma unroll
        for (int i = 0; i < 2; i++) {
            int r = r0 + ty + 32 * i; if (r >= so) continue;
            #pragma unroll
            for (int j = 0; j < 4; j++) {
                int cx = tx + 16 * j;
                if (cx < nn) { g_H[b][r][so + cx] = -t2v[i][j]; g_H[b][so + cx][r] = -t2v[i][j]; }
            }
        }
    }
    __syncthreads();
    #pragma unroll
    for (int i = 0; i < 2; i++)
        #pragma unroll
        for (int j = 0; j < 4; j++) As[(ty + 32 * i) * PAD + tx + 16 * j] = t2v[i][j];
    // phase B: H11[r][c] += sum_k T2[r][k] T1[c][k], double-buffered over c-steps
    #pragma unroll
    for (int q = 0; q < 2; q++) {
        int idx = t + 512 * q; int r = idx >> 4, f = (idx & 15) * 4;
        cpa16(&Bb[r * PAD + f], &g_T1[b][cbase * 64 + r][f]);
    }
    cpcommit();
    for (int step = 0; step < csteps; step++) {
        int cur = step & 1;
        if (step + 1 < csteps) {
            int c0n = (cbase + step + 1) * 64;
            #pragma unroll
            for (int q = 0; q < 2; q++) {
                int idx = t + 512 * q; int r = idx >> 4, f = (idx & 15) * 4;
                cpa16(&Bb[(cur ^ 1) * TILE + r * PAD + f], &g_T1[b][c0n + r][f]);
            }
            cpcommit(); cpwait1();
        } else cpwait0();
        __syncthreads();
        const float* Bs = Bb + cur * TILE;
        u64_t accb[2][4] = {};
        MICRO(As, Bs, accb)
        int c0 = (cbase + step) * 64;
        #pragma unroll
        for (int i = 0; i < 2; i++) {
            int r = r0 + ty + 32 * i; if (r >= so) continue;
            #pragma unroll
            for (int j = 0; j < 4; j++) {
                int c = c0 + tx + 16 * j; if (c >= so) continue;
                g_H[b][r][c] += acc2sum(accb[i][j]);
            }
        }
        __syncthreads();
    }
}

#define MATVEC16(W, VEC, OUTVAR)                                       \
    {                                                                  \
        float a0 = 0.f, a1 = 0.f, a2 = 0.f, a3 = 0.f;                  \
        for (int j0 = 0; j0 < spad; j0 += 16) {                        \
            _Pragma("unroll")                                          \
            for (int jj = 0; jj < 16; jj += 4) {                       \
                a0 = fmaf(W[b][j0 + jj + 0][t], VEC[j0 + jj + 0], a0); \
                a1 = fmaf(W[b][j0 + jj + 1][t], VEC[j0 + jj + 1], a1); \
                a2 = fmaf(W[b][j0 + jj + 2][t], VEC[j0 + jj + 2], a2); \
                a3 = fmaf(W[b][j0 + jj + 3][t], VEC[j0 + jj + 3], a3); \
            }                                                          \
        }                                                              \
        OUTVAR = ((a0 + a1) + (a2 + a3));                              \
    }

// ---------------- solve (+refine last) + radix top-32 + residual / out ----------------
// grid BD, block 512
__global__ __launch_bounds__(512) void k_solve(const float* __restrict__ meas,
                                               float* __restrict__ out, int last) {
    int b = blockIdx.x;
    if (g_done[b]) return;
    int s = g_scount[b];
    int spad = (s + 15) & ~15;
    int t = threadIdx.x, lane = t & 31, wd = t >> 5;
    __shared__ float cs[SMX], sl[SMX], rs[SMX];
    __shared__ int hist[256];
    __shared__ unsigned sh_pref; __shared__ int sh_need;
    __shared__ int eqsl[SMX]; __shared__ int neq; __shared__ unsigned char self_[SMX];
    __shared__ int wsum[16]; __shared__ float pv[KK]; __shared__ int pp[KK];
    __shared__ float rn[16];
    cs[t] = (t < s) ? g_c[b][t] : 0.f;
    __syncthreads();
    float v0;
    MATVEC16(g_H, cs, v0)
    float solv;
    if (last) {
        sl[t] = (t < s) ? v0 : 0.f;
        __syncthreads();
        float v1;
        MATVEC16(g_G, sl, v1)
        rs[t] = (t < s) ? (cs[t] - v1) : 0.f;
        __syncthreads();
        float v2;
        MATVEC16(g_H, rs, v2)
        solv = (t < s) ? (sl[t] + v2) : 0.f;
    } else {
        solv = (t < s) ? v0 : 0.f;
    }
    unsigned key = (t < s) ? __float_as_uint(fabsf(solv)) : 0u;
    unsigned pref = 0; int need = KK;
    for (int shift = 24; shift >= 0; shift -= 8) {
        unsigned mhi = (shift == 24) ? 0u : (0xFFFFFFFFu << (shift + 8));
        if (t < 256) hist[t] = 0;
        __syncthreads();
        if ((key & mhi) == pref) atomicAdd(&hist[(key >> shift) & 255], 1);
        __syncthreads();
        if (t < 32) {
            int base = 255 - 8 * t;
            int cnt[8]; int ssum = 0;
            #pragma unroll
            for (int q = 0; q < 8; q++) { cnt[q] = hist[base - q]; ssum += cnt[q]; }
            int incl = ssum;
            #pragma unroll
            for (int off = 1; off < 32; off <<= 1) {
                int v = __shfl_up_sync(0xffffffffu, incl, off);
                if (t >= off) incl += v;
            }
            int excl = incl - ssum;
            if (excl < need && need <= incl) {
                int cum = excl;
                #pragma unroll
                for (int q = 0; q < 8; q++) {
                    cum += cnt[q];
                    if (cum >= need) {
                        sh_pref = pref | ((unsigned)(base - q) << shift);
                        sh_need = need - (cum - cnt[q]);
                        break;
                    }
                }
            }
        }
        __syncthreads();
        pref = sh_pref; need = sh_need;
        __syncthreads();
    }
    unsigned T = pref;
    bool isgt = (key > T) && (t < s);
    bool iseq = (key == T) && (t < s);
    self_[t] = isgt ? 1 : 0;
    if (t == 0) neq = 0;
    __syncthreads();
    if (iseq) { int p = atomicAdd(&neq, 1); eqsl[p] = t; }
    __syncthreads();
    if (t == 0) {
        for (int r = 0; r < need; r++) {
            int bestc = 0x7fffffff, bi = -1;
            for (int q = 0; q < neq; q++) {
                int slot = eqsl[q];
                if (!self_[slot]) { int c = g_suplist[b][slot]; if (c < bestc) { bestc = c; bi = slot; } }
            }
            if (bi >= 0) self_[bi] = 1;
        }
    }
    __syncthreads();
    bool sel = self_[t] != 0;
    unsigned bsel = __ballot_sync(0xffffffffu, sel);
    if (lane == 0) wsum[wd] = __popc(bsel);
    __syncthreads();
    int pre = 0;
    #pragma unroll
    for (int w = 0; w < 16; w++) if (w < wd) pre += wsum[w];
    int rank = pre + __popc(bsel & ((1u << lane) - 1));
    if (sel) { pp[rank] = t; pv[rank] = solv; }
    __syncthreads();
    if (last) {
        if (t < KK) out[(size_t)b * ND + g_suplist[b][pp[t]]] = pv[t];
    } else {
        float nrm = 0.f;
        for (int m = t; m < MD; m += 512) {
            float r = meas[(size_t)b * MD + m];
            #pragma unroll
            for (int j = 0; j < KK; j++) r = fmaf(-pv[j], g_P[b][pp[j]][m], r);
            g_rT[m][b] = r;
            nrm = fmaf(r, r, nrm);
        }
        #pragma unroll
        for (int off = 16; off; off >>= 1) nrm += __shfl_down_sync(0xffffffffu, nrm, off);
        if (lane == 0) rn[wd] = nrm;
        __syncthreads();
        if (t == 0) {
            float tot = 0.f;
            #pragma unroll
            for (int w = 0; w < 16; w++) tot += rn[w];
            if (tot < TOLSQ) g_done[b] = 1;
        }
    }
}

extern "C" void kernel_launch(void* const* d_in, const int* in_sizes, int n_in,
                              void* d_out, int out_size) {
    const float* meas = (const float*)d_in[0];
    const float* A    = (const float*)d_in[1];
    if (n_in >= 2 && in_sizes[0] != BD * MD) {
        meas = (const float*)d_in[1];
        A    = (const float*)d_in[0];
    }
    float* out = (float*)d_out;

    int PX = 65536 + 16 * 32 * 17 * 4;        // 100352
    int TS = 4096 * 4 + 4096 * 4;             // 32768
    int GS = 4 * TILE * 4;                    // 69632
    int G3 = 3 * TILE * 4;                    // 52224
    cudaFuncSetAttribute(k_proxy, cudaFuncAttributeMaxDynamicSharedMemorySize, PX);
    cudaFuncSetAttribute(k_topk,  cudaFuncAttributeMaxDynamicSharedMemorySize, TS);
    cudaFuncSetAttribute(k_gram,  cudaFuncAttributeMaxDynamicSharedMemorySize, GS);
    cudaFuncSetAttribute(k_T1,    cudaFuncAttributeMaxDynamicSharedMemorySize, GS);
    cudaFuncSetAttribute(k_SSinv, cudaFuncAttributeMaxDynamicSharedMemorySize, GS);
    cudaFuncSetAttribute(k_T2H11, cudaFuncAttributeMaxDynamicSharedMemorySize, G3);

    k_transpose<<<dim3(ND / 32, MD / 32), dim3(32, 8)>>>(A);
    k_init<<<2048, 256>>>(meas, out);
    for (int it = 0; it < NITER; it++) {
        int last = (it == NITER - 1) ? 1 : 0;
        k_proxy<<<128, 512, PX>>>(A, it == 0 ? 1 : 0);
        k_topk<<<BD, 512, TS>>>();
        k_pack<<<dim3(BD, 64), 128>>>();
        k_gram<<<dim3(BD, 8, 4), 512, GS>>>();
        k_T1<<<dim3(BD, 8, 2), 512, GS>>>();
        k_SSinv<<<BD, 512, GS>>>();
        k_T2H11<<<dim3(BD, 8, 2), 512, G3>>>();
        k_solve<<<BD, 512>>>(meas, out, last);
    }
}

// round 13
// speedup vs baseline: 1.0891x; 1.0891x over previous
#include <cuda_runtime.h>
#include <math.h>

#define MD 1024
#define ND 4096
#define BD 16
#define KK 32
#define SMX 512
#define NITER 8
#define TOLSQ (1e-6f * 1e-6f)
#define PAD 68
#define TILE (64 * PAD)

typedef unsigned long long u64_t;
__device__ __forceinline__ void fma2(u64_t &d, u64_t a, u64_t b) {
    asm("fma.rn.f32x2 %0, %1, %2, %0;" : "+l"(d) : "l"(a), "l"(b));
}
__device__ __forceinline__ float acc2sum(u64_t v) {
    float lo, hi; asm("mov.b64 {%0,%1}, %2;" : "=f"(lo), "=f"(hi) : "l"(v)); return lo + hi;
}
__device__ __forceinline__ u64_t pack2(float x) {
    u64_t r; asm("mov.b64 %0, {%1,%1};" : "=l"(r) : "f"(x)); return r;
}
__device__ __forceinline__ void cpa16(float* dst, const float* src) {
    unsigned d = (unsigned)__cvta_generic_to_shared(dst);
    asm volatile("cp.async.cg.shared.global [%0], [%1], 16;" :: "r"(d), "l"(src) : "memory");
}
__device__ __forceinline__ void cpcommit() { asm volatile("cp.async.commit_group;" ::: "memory"); }
__device__ __forceinline__ void cpwait0()  { asm volatile("cp.async.wait_group 0;" ::: "memory"); }
__device__ __forceinline__ void cpwait1()  { asm volatile("cp.async.wait_group 1;" ::: "memory"); }

// ---------------- persistent device state ----------------
__device__ __align__(16) float g_AT[ND][MD];
__device__ __align__(16) float g_rT[MD][BD];
__device__ __align__(16) float g_proxy[BD][ND];
__device__ __align__(16) float g_ATy[BD][ND];       // A^T y (saved from iter-1 proxy)
__device__ unsigned char g_support[BD][ND];
__device__ int   g_suplist[BD][SMX];                // zero-initialized (safe indices)
__device__ int   g_scount[BD], g_sold[BD], g_done[BD];
__device__ __align__(16) float g_P[BD][SMX][MD];    // packed support columns
__device__ __align__(16) float g_G[BD][SMX][SMX];   // zero beyond s (invariant)
__device__ __align__(16) float g_H[BD][SMX][SMX];   // zero beyond s (invariant)
__device__ float g_c[BD][SMX];
__device__ __align__(16) float g_T1[BD][SMX][64];   // zeroed each iter (in k_gram)
__device__ __align__(16) float g_Sinv[BD][64][64];

// ---------------- one-time: transpose A ----------------
__global__ void k_transpose(const float* __restrict__ A) {
    __shared__ float tile[32][33];
    int nb = blockIdx.x * 32, mb = blockIdx.y * 32;
    int tx = threadIdx.x, ty = threadIdx.y;
    for (int i = ty; i < 32; i += 8)
        tile[i][tx] = A[(size_t)(mb + i) * ND + nb + tx];
    __syncthreads();
    for (int i = ty; i < 32; i += 8)
        g_AT[nb + i][mb + tx] = tile[tx][i];
}

// ---------------- init ----------------
__global__ void k_init(const float* __restrict__ meas, float* __restrict__ out) {
    long i = (long)blockIdx.x * blockDim.x + threadIdx.x;
    long stride = (long)gridDim.x * blockDim.x;
    float4 z4 = make_float4(0.f, 0.f, 0.f, 0.f);
    long ng = (long)BD * SMX * SMX / 4;
    float4* pg = (float4*)g_G; for (long k = i; k < ng; k += stride) pg[k] = z4;
    float4* ph = (float4*)g_H; for (long k = i; k < ng; k += stride) ph[k] = z4;
    for (long k = i; k < (long)BD * ND; k += stride) {
        g_support[k / ND][k % ND] = 0;
        out[k] = 0.f;
    }
    for (long k = i; k < (long)BD * SMX; k += stride) g_suplist[k / SMX][k % SMX] = 0;
    if (i < BD * MD) { int b = (int)(i / MD), m = (int)(i % MD); g_rT[m][b] = meas[b * MD + m]; }
    if (i < BD) { g_scount[i] = 0; g_sold[i] = 0; g_done[i] = 0; }
}

// ---------------- proxy: proxy[b][n] = sum_m A[m][n] r[m][b]; save=1 also stores ATy ----------------
// grid 128 (n-chunks of 32), block 512 = 32 n-lanes x 16 m-slices
__global__ __launch_bounds__(512) void k_proxy(const float* __restrict__ A, int save) {
    extern __shared__ float smf[];
    u64_t* rsh = (u64_t*)smf;            // [1024][8] u64 = 64KB
    float* psum = smf + 16384;           // [16][32][17]
    int t = threadIdx.x;
    int n0 = blockIdx.x * 32;
    const u64_t* rg = (const u64_t*)g_rT;
    for (int i = t; i < 8192; i += 512) rsh[i] = rg[i];
    __syncthreads();
    int nl = t & 31, mg = t >> 5;
    u64_t acc[8] = {};
    const float* Ac = A + (size_t)(mg * 64) * ND + n0 + nl;
    #pragma unroll 4
    for (int mm = 0; mm < 64; mm++) {
        float a = Ac[(size_t)mm * ND];
        u64_t ad = pack2(a);
        const ulonglong2* rp = (const ulonglong2*)&rsh[(mg * 64 + mm) * 8];
        ulonglong2 r01 = rp[0], r23 = rp[1], r45 = rp[2], r67 = rp[3];
        fma2(acc[0], ad, r01.x); fma2(acc[1], ad, r01.y);
        fma2(acc[2], ad, r23.x); fma2(acc[3], ad, r23.y);
        fma2(acc[4], ad, r45.x); fma2(acc[5], ad, r45.y);
        fma2(acc[6], ad, r67.x); fma2(acc[7], ad, r67.y);
    }
    #pragma unroll
    for (int bp = 0; bp < 8; bp++) {
        float lo, hi; asm("mov.b64 {%0,%1}, %2;" : "=f"(lo), "=f"(hi) : "l"(acc[bp]));
        psum[(mg * 32 + nl) * 17 + 2 * bp]     = lo;
        psum[(mg * 32 + nl) * 17 + 2 * bp + 1] = hi;
    }
    __syncthreads();
    int b = t >> 5, lane = t & 31;
    float s = 0.f;
    #pragma unroll
    for (int m2 = 0; m2 < 16; m2++) s += psum[(m2 * 32 + lane) * 17 + b];
    g_proxy[b][n0 + lane] = s;
    if (save) g_ATy[b][n0 + lane] = s;
}

// ---------------- suffix-scan boundary select over 2048 buckets ----------------
__device__ __forceinline__ void suffix_select(const int* hist, int need, int t, int lane, int wd,
                                              int* wtot, int* outB, int* outNeed) {
    int base = 2047 - 4 * t;
    int c[4];
    #pragma unroll
    for (int q = 0; q < 4; q++) c[q] = hist[base - q];
    int ssum = c[0] + c[1] + c[2] + c[3];
    int incl = ssum;
    #pragma unroll
    for (int off = 1; off < 32; off <<= 1) {
        int v = __shfl_up_sync(0xffffffffu, incl, off);
        if (lane >= off) incl += v;
    }
    if (lane == 31) wtot[wd] = incl;
    __syncthreads();
    int wpre = 0;
    #pragma unroll
    for (int w = 0; w < 16; w++) if (w < wd) wpre += wtot[w];
    incl += wpre;
    int excl = incl - ssum;
    if (excl < need && need <= incl) {
        int cum = excl;
        #pragma unroll
        for (int q = 0; q < 4; q++) {
            cum += c[q];
            if (cum >= need) { *outB = base - q; *outNeed = need - (cum - c[q]); break; }
        }
    }
    __syncthreads();
}

// ---------------- topk: 3-pass radix + support update + pack copy + c gather ----------------
// grid BD, block 512
__global__ __launch_bounds__(512) void k_topk(void) {
    int b = blockIdx.x;
    if (g_done[b]) return;
    extern __shared__ float smf[];
    unsigned* keys = (unsigned*)smf;           // [4096]
    int* cand = (int*)(smf + 4096);            // [4096]
    __shared__ int hist[2048];
    __shared__ int wtot[16];
    __shared__ int sh_B, sh_need, sh_L;
    __shared__ int sh_app, sh_sold, sh_neq;
    __shared__ int eqlist[128];
    int t = threadIdx.x, lane = t & 31, wd = t >> 5;
    for (int n = t; n < ND; n += 512) keys[n] = __float_as_uint(fabsf(g_proxy[b][n]));
    for (int i = t; i < 2048; i += 512) hist[i] = 0;
    if (t == 0) { sh_sold = g_scount[b]; sh_app = sh_sold; sh_neq = 0; sh_L = 0; }
    __syncthreads();
    // pass 1: bits 31..21, warp-aggregated atomics
    for (int n = t; n < ND; n += 512) {
        unsigned d = keys[n] >> 21;
        unsigned mk = __match_any_sync(0xffffffffu, d);
        if ((mk & ((1u << lane) - 1)) == 0) atomicAdd(&hist[d], __popc(mk));
    }
    __syncthreads();
    suffix_select(hist, 2 * KK, t, lane, wd, wtot, &sh_B, &sh_need);
    unsigned pref = (unsigned)sh_B << 21;
    int need = sh_need;
    __syncthreads();
    // compact boundary-bucket candidates
    for (int n = t; n < ND; n += 512)
        if ((keys[n] >> 21) == (pref >> 21)) { int p = atomicAdd(&sh_L, 1); cand[p] = n; }
    __syncthreads();
    int L = sh_L;
    // pass 2: bits 20..10 over candidates
    for (int i = t; i < 2048; i += 512) hist[i] = 0;
    __syncthreads();
    for (int i = t; i < L; i += 512) atomicAdd(&hist[(keys[cand[i]] >> 10) & 2047u], 1);
    __syncthreads();
    suffix_select(hist, need, t, lane, wd, wtot, &sh_B, &sh_need);
    pref |= (unsigned)sh_B << 10;
    need = sh_need;
    __syncthreads();
    // pass 3: bits 9..0
    for (int i = t; i < 2048; i += 512) hist[i] = 0;
    __syncthreads();
    for (int i = t; i < L; i += 512) {
        unsigned k = keys[cand[i]];
        if ((k >> 10) == (pref >> 10)) atomicAdd(&hist[k & 1023u], 1);
    }
    __syncthreads();
    suffix_select(hist, need, t, lane, wd, wtot, &sh_B, &sh_need);
    unsigned T = pref | (unsigned)sh_B;
    need = sh_need;
    __syncthreads();
    // select key > T (unordered append; slot order irrelevant to the linear algebra)
    for (int n = t; n < ND; n += 512) {
        if (keys[n] > T && !g_support[b][n]) {
            g_support[b][n] = 1;
            int p = atomicAdd(&sh_app, 1);
            g_suplist[b][p] = n;
        }
    }
    for (int i = t; i < L; i += 512) {
        int n = cand[i];
        if (keys[n] == T) { int q = atomicAdd(&sh_neq, 1); if (q < 128) eqlist[q] = n; }
    }
    __syncthreads();
    if (t == 0) {
        int ne = sh_neq < 128 ? sh_neq : 128;
        for (int r = 0; r < need; r++) {           // jax ties: smallest index first
            int best = 0x7fffffff, bi = -1;
            for (int q = 0; q < ne; q++) { int n = eqlist[q]; if (n >= 0 && n < best) { best = n; bi = q; } }
            if (bi < 0) break;
            eqlist[bi] = -1;
            if (!g_support[b][best]) { g_support[b][best] = 1; g_suplist[b][sh_app++] = best; }
        }
        g_sold[b] = sh_sold;
        g_scount[b] = sh_app;
    }
    __syncthreads();
    int so = sh_sold, s = sh_app, nn = s - so;
    // c for new slots: gather from ATy (c_p = (A^T y)[col])
    for (int p = so + t; p < s; p += 512)
        g_c[b][p] = g_ATy[b][g_suplist[b][p]];
    // fused pack: pure copy of new columns (warp per column, high MLP)
    for (int p = wd; p < nn; p += 16) {
        int col = g_suplist[b][so + p];
        const float4* Ac = (const float4*)g_AT[col];
        float4* Pd = (float4*)g_P[b][so + p];
        float4 v[8];
        #pragma unroll
        for (int i = 0; i < 8; i++) v[i] = Ac[i * 32 + lane];
        #pragma unroll
        for (int i = 0; i < 8; i++) Pd[i * 32 + lane] = v[i];
    }
}

// ======== 64x64 microkernel: 512 thr, 2x4 accs, conflict-free LDS.128 ========
#define MICRO(AS, BS, ACC)                                                     \
    {                                                                          \
        _Pragma("unroll")                                                      \
        for (int k4 = 0; k4 < 16; k4++) {                                      \
            ulonglong2 rv[2], cv[4];                                           \
            _Pragma("unroll")                                                  \
            for (int i = 0; i < 2; i++)                                        \
                rv[i] = *(const ulonglong2*)&(AS)[(ty + 32 * i) * PAD + k4 * 4]; \
            _Pragma("unroll")                                                  \
            for (int j = 0; j < 4; j++)                                        \
                cv[j] = *(const ulonglong2*)&(BS)[(tx + 16 * j) * PAD + k4 * 4]; \
            _Pragma("unroll")                                                  \
            for (int i = 0; i < 2; i++)                                        \
                _Pragma("unroll")                                              \
                for (int j = 0; j < 4; j++) {                                  \
                    fma2(ACC[i][j], rv[i].x, cv[j].x);                         \
                    fma2(ACC[i][j], rv[i].y, cv[j].y);                         \
                }                                                              \
        }                                                                      \
    }

// pipelined 64xNSx64 GEMM with uniform row strides
__device__ __forceinline__ void pipe_gemm(const float* A0, int As_, const float* B0, int Bs_,
                                          int NS, float* sm, u64_t (&acc)[2][4],
                                          int t, int ty, int tx) {
    float* Ab = sm; float* Bb = sm + 2 * TILE;
    #pragma unroll
    for (int q = 0; q < 2; q++) {
        int idx = t + 512 * q; int r = idx >> 4, f = (idx & 15) * 4;
        cpa16(&Ab[r * PAD + f], A0 + (long)r * As_ + f);
        cpa16(&Bb[r * PAD + f], B0 + (long)r * Bs_ + f);
    }
    cpcommit();
    for (int step = 0; step < NS; step++) {
        int cur = step & 1;
        if (step + 1 < NS) {
            int k0 = (step + 1) * 64;
            #pragma unroll
            for (int q = 0; q < 2; q++) {
                int idx = t + 512 * q; int r = idx >> 4, f = (idx & 15) * 4;
                cpa16(&Ab[(cur ^ 1) * TILE + r * PAD + f], A0 + (long)r * As_ + k0 + f);
                cpa16(&Bb[(cur ^ 1) * TILE + r * PAD + f], B0 + (long)r * Bs_ + k0 + f);
            }
            cpcommit(); cpwait1();
        } else cpwait0();
        __syncthreads();
        const float* As = Ab + cur * TILE;
        const float* Bs = Bb + cur * TILE;
        MICRO(As, Bs, acc)
        __syncthreads();
    }
}

// ---------------- gram: contiguous g_P rows, k-split 4, atomic accumulate ----------------
// grid (BD, 8, 4), block 512
__global__ __launch_bounds__(512) void k_gram(void) {
    int b = blockIdx.x;
    if (g_done[b]) return;
    int so = g_sold[b], s = g_scount[b], nn = s - so;
    if (nn == 0) return;
    int t = threadIdx.x;
    if (blockIdx.y == 0 && blockIdx.z == 0) {   // zero T1 for the next kernel
        float4 z4 = make_float4(0.f, 0.f, 0.f, 0.f);
        float4* p = (float4*)g_T1[b];
        for (int i = t; i < SMX * 64 / 4; i += 512) p[i] = z4;
    }
    int c0 = blockIdx.y * 64;
    if (c0 >= s) return;
    extern __shared__ float sm[];
    int ty = t >> 4, tx = t & 15;
    int kz = blockIdx.z * 256;
    u64_t acc[2][4] = {};
    pipe_gemm(&g_P[b][so][kz], MD, &g_P[b][c0][kz], MD, 4, sm, acc, t, ty, tx);
    #pragma unroll
    for (int i = 0; i < 2; i++) {
        int r = ty + 32 * i; if (r >= nn) continue;
        #pragma unroll
        for (int j = 0; j < 4; j++) {
            int c = c0 + tx + 16 * j; if (c >= s) continue;
            float v = acc2sum(acc[i][j]);
            atomicAdd(&g_G[b][so + r][c], v);
            if (c < so) atomicAdd(&g_G[b][c][so + r], v);  // mirror (new-new covered directly)
        }
    }
}

// ---------------- T1: k-split 2, atomic into pre-zeroed T1 ----------------
// grid (BD, 8, 2), block 512
__global__ __launch_bounds__(512) void k_T1(void) {
    int b = blockIdx.x;
    if (g_done[b]) return;
    int so = g_sold[b], s = g_scount[b], nn = s - so;
    if (nn == 0) return;
    int r0 = blockIdx.y * 64;
    if (r0 >= so) return;
    int NS = (so + 63) >> 6;
    int nsa = (NS + 1) >> 1;
    int base = (blockIdx.z == 0) ? 0 : nsa;
    int steps = (blockIdx.z == 0) ? nsa : NS - nsa;
    if (steps <= 0) return;
    extern __shared__ float sm[];
    int t = threadIdx.x, ty = t >> 4, tx = t & 15;
    u64_t acc[2][4] = {};
    pipe_gemm(&g_G[b][so][base * 64], SMX, &g_H[b][r0][base * 64], SMX, steps, sm, acc, t, ty, tx);
    #pragma unroll
    for (int i = 0; i < 2; i++) {
        int c = ty + 32 * i;
        #pragma unroll
        for (int j = 0; j < 4; j++)
            atomicAdd(&g_T1[b][r0 + tx + 16 * j][c], acc2sum(acc[i][j]));
    }
}

// ---------------- SSinv: S = G22 - G21 T1 -> GJ inverse -> Sinv, H22 ----------------
// grid BD, block 512
__global__ __launch_bounds__(512) void k_SSinv(void) {
    int b = blockIdx.x;
    if (g_done[b]) return;
    int so = g_sold[b], s = g_scount[b], nn = s - so;
    if (nn == 0) return;
    __shared__ float Gs[64][65], Ts[64][65];
    __shared__ float pivrow[128], fcol[64], sh_piv;
    int t = threadIdx.x;
    int i = t >> 3, jg = t & 7;
    float accs[8] = {};
    for (int k0 = 0; k0 < so; k0 += 64) {
        for (int idx = t; idx < 64 * 64; idx += 512) {
            int rr = idx >> 6, kk = idx & 63;
            Gs[rr][kk] = g_G[b][so + rr][k0 + kk];
            Ts[rr][kk] = g_T1[b][k0 + rr][kk];
        }
        __syncthreads();
        #pragma unroll 8
        for (int k = 0; k < 64; k++) {
            float gv = Gs[i][k];
            #pragma unroll
            for (int jj = 0; jj < 8; jj++) accs[jj] = fmaf(gv, Ts[k][jg * 8 + jj], accs[jj]);
        }
        __syncthreads();
    }
    #pragma unroll
    for (int jj = 0; jj < 8; jj++) {
        int j = jg * 8 + jj;
        float v;
        if (i < nn && j < nn) v = g_G[b][so + i][so + j] - accs[jj];
        else v = (i == j) ? 1.f : 0.f;
        Gs[i][j] = v;
    }
    __syncthreads();
    int row = t >> 3, cg = t & 7;
    float a[16];
    #pragma unroll
    for (int cc = 0; cc < 16; cc++) {
        int c = cg * 16 + cc;
        a[cc] = (c < 64) ? Gs[row][c] : ((c - 64 == row) ? 1.f : 0.f);
    }
    __syncthreads();
    for (int j = 0; j < 64; j++) {
        if (row == j && cg == (j >> 4)) sh_piv = a[j & 15];
        __syncthreads();
        float inv = 1.f / sh_piv;
        if (row == j) {
            #pragma unroll
            for (int cc = 0; cc < 16; cc++) { a[cc] *= inv; pivrow[cg * 16 + cc] = a[cc]; }
        }
        if (cg == (j >> 4)) fcol[row] = a[j & 15];
        __syncthreads();
        float f = (row == j) ? 0.f : fcol[row];
        #pragma unroll
        for (int cc = 0; cc < 16; cc++) a[cc] = fmaf(-f, pivrow[cg * 16 + cc], a[cc]);
    }
    __syncthreads();
    #pragma unroll
    for (int cc = 0; cc < 16; cc++) {
        int c = cg * 16 + cc;
        if (c >= 64) {
            int j = c - 64;
            g_Sinv[b][row][j] = a[cc];
            if (row < nn && j < nn) g_H[b][so + row][so + j] = a[cc];
        }
    }
}

// ---------------- T2 + H11 (c-split 2, disjoint tiles) ----------------
// grid (BD, 8, 2), block 512
__global__ __launch_bounds__(512) void k_T2H11(void) {
    int b = blockIdx.x;
    if (g_done[b]) return;
    int so = g_sold[b], s = g_scount[b], nn = s - so;
    if (nn == 0) return;
    int r0 = blockIdx.y * 64;
    if (r0 >= so) return;
    int NSB = (so + 63) >> 6;
    int nsa = (NSB + 1) >> 1;
    int cbase = (blockIdx.z == 0) ? 0 : nsa;
    int csteps = (blockIdx.z == 0) ? nsa : NSB - nsa;
    if (csteps <= 0) return;
    extern __shared__ float sm[];
    float* As = sm; float* Bb = sm + TILE;
    int t = threadIdx.x, ty = t >> 4, tx = t & 15;
    // phase A: T2[r][c] = sum_k T1[r][k] Sinv[c][k]
    #pragma unroll
    for (int q = 0; q < 2; q++) {
        int idx = t + 512 * q; int r = idx >> 4, f = (idx & 15) * 4;
        cpa16(&As[r * PAD + f], &g_T1[b][r0 + r][f]);
        cpa16(&Bb[r * PAD + f], &g_Sinv[b][r][f]);
    }
    cpcommit(); cpwait0();
    __syncthreads();
    u64_t acc[2][4] = {};
    MICRO(As, Bb, acc)
    float t2v[2][4];
    #pragma unroll
    for (int i = 0; i < 2; i++)
        #pragma unroll
        for (int j = 0; j < 4; j++) t2v[i][j] = acc2sum(acc[i][j]);
    if (blockIdx.z == 0) {
        #pragma unroll
        for (int i = 0; i < 2; i++) {
            int r = r0 + ty + 32 * i; if (r >= so) continue;
            #pragma unroll
            for (int j = 0; j < 4; j++) {
                int cx = tx + 16 * j;
                if (cx < nn) { g_H[b][r][so + cx] = -t2v[i][j]; g_H[b][so + cx][r] = -t2v[i][j]; }
            }
        }
    }
    __syncthreads();
    #pragma unroll
    for (int i = 0; i < 2; i++)
        #pragma unroll
        for (int j = 0; j < 4; j++) As[(ty + 32 * i) * PAD + tx + 16 * j] = t2v[i][j];
    // phase B: H11[r][c] += sum_k T2[r][k] T1[c][k], double-buffered over c-steps
    #pragma unroll
    for (int q = 0; q < 2; q++) {
        int idx = t + 512 * q; int r = idx >> 4, f = (idx & 15) * 4;
        cpa16(&Bb[r * PAD + f], &g_T1[b][cbase * 64 + r][f]);
    }
    cpcommit();
    for (int step = 0; step < csteps; step++) {
        int cur = step & 1;
        if (step + 1 < csteps) {
            int c0n = (cbase + step + 1) * 64;
            #pragma unroll
            for (int q = 0; q < 2; q++) {
                int idx = t + 512 * q; int r = idx >> 4, f = (idx & 15) * 4;
                cpa16(&Bb[(cur ^ 1) * TILE + r * PAD + f], &g_T1[b][c0n + r][f]);
            }
            cpcommit(); cpwait1();
        } else cpwait0();
        __syncthreads();
        const float* Bs = Bb + cur * TILE;
        u64_t accb[2][4] = {};
        MICRO(As, Bs, accb)
        int c0 = (cbase + step) * 64;
        #pragma unroll
        for (int i = 0; i < 2; i++) {
            int r = r0 + ty + 32 * i; if (r >= so) continue;
            #pragma unroll
            for (int j = 0; j < 4; j++) {
                int c = c0 + tx + 16 * j; if (c >= so) continue;
                g_H[b][r][c] += acc2sum(accb[i][j]);
            }
        }
        __syncthreads();
    }
}

#define MATVEC16(W, VEC, OUTVAR)                                       \
    {                                                                  \
        float a0 = 0.f, a1 = 0.f, a2 = 0.f, a3 = 0.f;                  \
        for (int j0 = 0; j0 < spad; j0 += 16) {                        \
            _Pragma("unroll")                                          \
            for (int jj = 0; jj < 16; jj += 4) {                       \
                a0 = fmaf(W[b][j0 + jj + 0][t], VEC[j0 + jj + 0], a0); \
                a1 = fmaf(W[b][j0 + jj + 1][t], VEC[j0 + jj + 1], a1); \
                a2 = fmaf(W[b][j0 + jj + 2][t], VEC[j0 + jj + 2], a2); \
                a3 = fmaf(W[b][j0 + jj + 3][t], VEC[j0 + jj + 3], a3); \
            }                                                          \
        }                                                              \
        OUTVAR = ((a0 + a1) + (a2 + a3));                              \
    }

// ---------------- solve (+refine last) + radix top-32 + residual / out ----------------
// grid BD, block 512
__global__ __launch_bounds__(512) void k_solve(const float* __restrict__ meas,
                                               float* __restrict__ out, int last) {
    int b = blockIdx.x;
    if (g_done[b]) return;
    int s = g_scount[b];
    int spad = (s + 15) & ~15;
    int t = threadIdx.x, lane = t & 31, wd = t >> 5;
    __shared__ float cs[SMX], sl[SMX], rs[SMX];
    __shared__ int hist[256];
    __shared__ unsigned sh_pref; __shared__ int sh_need;
    __shared__ int eqsl[SMX]; __shared__ int neq; __shared__ unsigned char self_[SMX];
    __shared__ int wsum[16]; __shared__ float pv[KK]; __shared__ int pp[KK];
    __shared__ float rn[16];
    cs[t] = (t < s) ? g_c[b][t] : 0.f;
    __syncthreads();
    float v0;
    MATVEC16(g_H, cs, v0)
    float solv;
    if (last) {
        sl[t] = (t < s) ? v0 : 0.f;
        __syncthreads();
        float v1;
        MATVEC16(g_G, sl, v1)
        rs[t] = (t < s) ? (cs[t] - v1) : 0.f;
        __syncthreads();
        float v2;
        MATVEC16(g_H, rs, v2)
        solv = (t < s) ? (sl[t] + v2) : 0.f;
    } else {
        solv = (t < s) ? v0 : 0.f;
    }
    unsigned key = (t < s) ? __float_as_uint(fabsf(solv)) : 0u;
    unsigned pref = 0; int need = KK;
    for (int shift = 24; shift >= 0; shift -= 8) {
        unsigned mhi = (shift == 24) ? 0u : (0xFFFFFFFFu << (shift + 8));
        if (t < 256) hist[t] = 0;
        __syncthreads();
        if ((key & mhi) == pref) atomicAdd(&hist[(key >> shift) & 255], 1);
        __syncthreads();
        if (t < 32) {
            int base = 255 - 8 * t;
            int cnt[8]; int ssum = 0;
            #pragma unroll
            for (int q = 0; q < 8; q++) { cnt[q] = hist[base - q]; ssum += cnt[q]; }
            int incl = ssum;
            #pragma unroll
            for (int off = 1; off < 32; off <<= 1) {
                int v = __shfl_up_sync(0xffffffffu, incl, off);
                if (t >= off) incl += v;
            }
            int excl = incl - ssum;
            if (excl < need && need <= incl) {
                int cum = excl;
                #pragma unroll
                for (int q = 0; q < 8; q++) {
                    cum += cnt[q];
                    if (cum >= need) {
                        sh_pref = pref | ((unsigned)(base - q) << shift);
                        sh_need = need - (cum - cnt[q]);
                        break;
                    }
                }
            }
        }
        __syncthreads();
        pref = sh_pref; need = sh_need;
        __syncthreads();
    }
    unsigned T = pref;
    bool isgt = (key > T) && (t < s);
    bool iseq = (key == T) && (t < s);
    self_[t] = isgt ? 1 : 0;
    if (t == 0) neq = 0;
    __syncthreads();
    if (iseq) { int p = atomicAdd(&neq, 1); eqsl[p] = t; }
    __syncthreads();
    if (t == 0) {
        for (int r = 0; r < need; r++) {
            int bestc = 0x7fffffff, bi = -1;
            for (int q = 0; q < neq; q++) {
                int slot = eqsl[q];
                if (!self_[slot]) { int c = g_suplist[b][slot]; if (c < bestc) { bestc = c; bi = slot; } }
            }
            if (bi >= 0) self_[bi] = 1;
        }
    }
    __syncthreads();
    bool sel = self_[t] != 0;
    unsigned bsel = __ballot_sync(0xffffffffu, sel);
    if (lane == 0) wsum[wd] = __popc(bsel);
    __syncthreads();
    int pre = 0;
    #pragma unroll
    for (int w = 0; w < 16; w++) if (w < wd) pre += wsum[w];
    int rank = pre + __popc(bsel & ((1u << lane) - 1));
    if (sel) { pp[rank] = t; pv[rank] = solv; }
    __syncthreads();
    if (last) {
        if (t < KK) out[(size_t)b * ND + g_suplist[b][pp[t]]] = pv[t];
    } else {
        float nrm = 0.f;
        for (int m = t; m < MD; m += 512) {
            float r = meas[(size_t)b * MD + m];
            #pragma unroll
            for (int j = 0; j < KK; j++) r = fmaf(-pv[j], g_P[b][pp[j]][m], r);
            g_rT[m][b] = r;
            nrm = fmaf(r, r, nrm);
        }
        #pragma unroll
        for (int off = 16; off; off >>= 1) nrm += __shfl_down_sync(0xffffffffu, nrm, off);
        if (lane == 0) rn[wd] = nrm;
        __syncthreads();
        if (t == 0) {
            float tot = 0.f;
            #pragma unroll
            for (int w = 0; w < 16; w++) tot += rn[w];
            if (tot < TOLSQ) g_done[b] = 1;
        }
    }
}

extern "C" void kernel_launch(void* const* d_in, const int* in_sizes, int n_in,
                              void* d_out, int out_size) {
    const float* meas = (const float*)d_in[0];
    const float* A    = (const float*)d_in[1];
    if (n_in >= 2 && in_sizes[0] != BD * MD) {
        meas = (const float*)d_in[1];
        A    = (const float*)d_in[0];
    }
    float* out = (float*)d_out;

    int PX = 65536 + 16 * 32 * 17 * 4;        // 100352
    int TS = 4096 * 4 + 4096 * 4;             // 32768
    int GS = 4 * TILE * 4;                    // 69632
    int G3 = 3 * TILE * 4;                    // 52224
    cudaFuncSetAttribute(k_proxy, cudaFuncAttributeMaxDynamicSharedMemorySize, PX);
    cudaFuncSetAttribute(k_topk,  cudaFuncAttributeMaxDynamicSharedMemorySize, TS);
    cudaFuncSetAttribute(k_gram,  cudaFuncAttributeMaxDynamicSharedMemorySize, GS);
    cudaFuncSetAttribute(k_T1,    cudaFuncAttributeMaxDynamicSharedMemorySize, GS);
    cudaFuncSetAttribute(k_T2H11, cudaFuncAttributeMaxDynamicSharedMemorySize, G3);

    k_transpose<<<dim3(ND / 32, MD / 32), dim3(32, 8)>>>(A);
    k_init<<<2048, 256>>>(meas, out);
    for (int it = 0; it < NITER; it++) {
        int last = (it == NITER - 1) ? 1 : 0;
        k_proxy<<<128, 512, PX>>>(A, it == 0 ? 1 : 0);
        k_topk<<<BD, 512, TS>>>();
        k_gram<<<dim3(BD, 8, 4), 512, GS>>>();
        k_T1<<<dim3(BD, 8, 2), 512, GS>>>();
        k_SSinv<<<BD, 512>>>();
        k_T2H11<<<dim3(BD, 8, 2), 512, G3>>>();
        k_solve<<<BD, 512>>>(meas, out, last);
    }
}